// round 11
// baseline (speedup 1.0000x reference)
#include <cuda_runtime.h>
#include <cuda_bf16.h>
#include <math.h>
#include <stdint.h>

#define Bn 8
#define Hn 512
#define Ln 4096
#define NSt 32   // N/2 states

// y = gelu(conv(u,k) + D*u) stored as bf16 hi/lo split (hi + lo ~ fp32-23bit)
__device__ __nv_bfloat16 g_yh[Bn * Hn * Ln];
__device__ __nv_bfloat16 g_yl[Bn * Hn * Ln];

// ---------------------------------------------------------------------------
// Kernel 1: diagonal SSM recurrence + D skip + exact (erf) GELU.
// One warp per (b,h); lane n owns complex state n. Register-array
// recursive-halving reduction (31 shfl per 32 outputs).
// Emits y as bf16 (hi, lo) pair for the tensor-core GEMM.
// ---------------------------------------------------------------------------
__global__ void __launch_bounds__(128)
s4d_recurrence(const float* __restrict__ u,
               const float* __restrict__ log_dt,
               const float* __restrict__ C_re,
               const float* __restrict__ C_im,
               const float* __restrict__ log_A_real,
               const float* __restrict__ A_imag,
               const float* __restrict__ Dv)
{
    int warp = (blockIdx.x * blockDim.x + threadIdx.x) >> 5;
    int lane = threadIdx.x & 31;
    if (warp >= Bn * Hn) return;
    int b = warp / Hn;
    int h = warp % Hn;

    float dt  = expf(log_dt[h]);
    float Are = -expf(log_A_real[h * NSt + lane]);
    float Aim = A_imag[h * NSt + lane];
    float dAr = Are * dt, dAi = Aim * dt;
    float er  = expf(dAr);
    float sv, cv;
    sincosf(dAi, &sv, &cv);
    float wr = er * cv, wi = er * sv;          // w = exp(dt*A)
    float cr = C_re[h * NSt + lane];
    float ci = C_im[h * NSt + lane];
    // Ck = 2*C*(w-1)/A
    float m1r = wr - 1.0f;
    float nr  = cr * m1r - ci * wi;
    float ni  = cr * wi  + ci * m1r;
    float inv = 2.0f / (Are * Are + Aim * Aim);
    float Ckr = (nr * Are + ni * Aim) * inv;
    float Cki = (ni * Are - nr * Aim) * inv;

    float Dh = Dv[h];
    const float*   up  = u    + (size_t)(b * Hn + h) * Ln;
    __nv_bfloat16* yph = g_yh + (size_t)(b * Hn + h) * Ln;
    __nv_bfloat16* ypl = g_yl + (size_t)(b * Hn + h) * Ln;

    float sr = 0.0f, si = 0.0f;
    for (int l0 = 0; l0 < Ln; l0 += 32) {
        float uv = up[l0 + lane];
        float p[32];
        #pragma unroll
        for (int j = 0; j < 32; ++j) {
            float uj  = __shfl_sync(0xffffffffu, uv, j);
            float t   = fmaf(wr, sr, uj);
            float nsi = fmaf(wr, si, wi * sr);
            sr = fmaf(-wi, si, t);
            si = nsi;
            p[j] = fmaf(Ckr, sr, -(Cki * si));
        }
        #pragma unroll
        for (int mask = 16; mask >= 1; mask >>= 1) {
            bool hi = (lane & mask) != 0;
            #pragma unroll
            for (int j = 0; j < 32; ++j) {
                if (j >= mask) continue;
                float mine = hi ? p[j] : p[j + mask];
                float keep = hi ? p[j + mask] : p[j];
                p[j] = keep + __shfl_xor_sync(0xffffffffu, mine, mask);
            }
        }
        float yraw = fmaf(Dh, uv, p[0]);
        float yg   = yraw * normcdff(yraw);     // exact GELU
        __nv_bfloat16 hh = __float2bfloat16(yg);
        __nv_bfloat16 ll = __float2bfloat16(yg - __bfloat162float(hh));
        yph[l0 + lane] = hh;
        ypl[l0 + lane] = ll;
    }
}

// ---------------------------------------------------------------------------
// Kernel 2: tensor-core GEMM (2H x H) @ (H x L) + bias + GLU.
// bf16 split-precision: acc = Whi@Yhi + Whi@Ylo + Wlo@Yhi (fp32 accum).
// CTA tile: 64 h-rows (both a and g halves => 128 W rows) x 128 l-cols, KT=32.
// 8 warps: mpos = wid&3 (a0,a1,g0,g1 row quads of 32), npos = wid>>2.
// Epilogue: g-warps stage sigmoid(g+bg) in smem; a-warps multiply + store.
// ---------------------------------------------------------------------------
#define KT 32

struct SmemOps {
    __nv_bfloat16 Wh[128][40];   // [row][k], pad -> 80B stride (conflict-free)
    __nv_bfloat16 Wl[128][40];
    __nv_bfloat16 Yh[KT][136];   // [k][col], pad -> 272B stride
    __nv_bfloat16 Yl[KT][136];
};
union SmemGemm {
    SmemOps op;
    float   Gs[64][132];         // sigmoid(g) staging for GLU epilogue
};

__device__ __forceinline__ uint32_t sptr(const void* p) {
    return (uint32_t)__cvta_generic_to_shared(p);
}
__device__ __forceinline__ void ldsm_x4(uint32_t* r, uint32_t addr) {
    asm volatile("ldmatrix.sync.aligned.m8n8.x4.shared.b16 {%0,%1,%2,%3}, [%4];"
                 : "=r"(r[0]), "=r"(r[1]), "=r"(r[2]), "=r"(r[3]) : "r"(addr));
}
__device__ __forceinline__ void ldsm_x4t(uint32_t* r, uint32_t addr) {
    asm volatile("ldmatrix.sync.aligned.m8n8.x4.trans.shared.b16 {%0,%1,%2,%3}, [%4];"
                 : "=r"(r[0]), "=r"(r[1]), "=r"(r[2]), "=r"(r[3]) : "r"(addr));
}
__device__ __forceinline__ void mma16816(float* c, const uint32_t* a,
                                         uint32_t b0, uint32_t b1) {
    asm volatile(
        "mma.sync.aligned.m16n8k16.row.col.f32.bf16.bf16.f32 "
        "{%0,%1,%2,%3}, {%4,%5,%6,%7}, {%8,%9}, {%0,%1,%2,%3};"
        : "+f"(c[0]), "+f"(c[1]), "+f"(c[2]), "+f"(c[3])
        : "r"(a[0]), "r"(a[1]), "r"(a[2]), "r"(a[3]), "r"(b0), "r"(b1));
}

__global__ void __launch_bounds__(256, 2)
s4d_glu_gemm(const float* __restrict__ Wm,
             const float* __restrict__ bias,
             float* __restrict__ out)
{
    __shared__ SmemGemm sm;

    int b   = blockIdx.z;
    int h0  = blockIdx.y * 64;
    int c0  = blockIdx.x * 128;
    int tid = threadIdx.x;
    int wid = tid >> 5, lane = tid & 31;
    int mpos = wid & 3;          // 0,1 -> a rows; 2,3 -> g rows
    int npos = wid >> 2;         // 0,1 -> col halves of 64

    float acc[2][8][4];          // [mi (16-row tile)][n8 tile][frag]
    #pragma unroll
    for (int i = 0; i < 2; i++)
        #pragma unroll
        for (int j = 0; j < 8; j++)
            #pragma unroll
            for (int v = 0; v < 4; v++) acc[i][j][v] = 0.0f;

    // load mappings
    int wrow = tid >> 1;                 // 0..127 (W tile row)
    int wcol = (tid & 1) * 16;           // k offset within KT
    int grow = (wrow < 64) ? (h0 + wrow) : (Hn + h0 + wrow - 64);
    const float* wsrc = Wm + (size_t)grow * Hn;

    int yrow = tid >> 3;                 // 0..31
    int ycol = (tid & 7) * 16;           // 0..112

    const __nv_bfloat16* ysh = g_yh + (size_t)b * Hn * Ln;
    const __nv_bfloat16* ysl = g_yl + (size_t)b * Hn * Ln;

    for (int kt = 0; kt < Hn; kt += KT) {
        // --- stage W (fp32 -> bf16 hi/lo) ---
        #pragma unroll
        for (int j = 0; j < 4; j++) {
            float4 v = *(const float4*)&wsrc[kt + wcol + 4 * j];
            __nv_bfloat162 h0p = __floats2bfloat162_rn(v.x, v.y);
            __nv_bfloat162 h1p = __floats2bfloat162_rn(v.z, v.w);
            float lx = v.x - __bfloat162float(h0p.x);
            float ly = v.y - __bfloat162float(h0p.y);
            float lz = v.z - __bfloat162float(h1p.x);
            float lw = v.w - __bfloat162float(h1p.y);
            __nv_bfloat162 l0p = __floats2bfloat162_rn(lx, ly);
            __nv_bfloat162 l1p = __floats2bfloat162_rn(lz, lw);
            *(__nv_bfloat162*)&sm.op.Wh[wrow][wcol + 4 * j]     = h0p;
            *(__nv_bfloat162*)&sm.op.Wh[wrow][wcol + 4 * j + 2] = h1p;
            *(__nv_bfloat162*)&sm.op.Wl[wrow][wcol + 4 * j]     = l0p;
            *(__nv_bfloat162*)&sm.op.Wl[wrow][wcol + 4 * j + 2] = l1p;
        }
        // --- stage Y (already bf16 hi/lo) ---
        {
            size_t gy = (size_t)(kt + yrow) * Ln + c0 + ycol;
            uint4 vh0 = *(const uint4*)&ysh[gy];
            uint4 vh1 = *(const uint4*)&ysh[gy + 8];
            uint4 vl0 = *(const uint4*)&ysl[gy];
            uint4 vl1 = *(const uint4*)&ysl[gy + 8];
            *(uint4*)&sm.op.Yh[yrow][ycol]     = vh0;
            *(uint4*)&sm.op.Yh[yrow][ycol + 8] = vh1;
            *(uint4*)&sm.op.Yl[yrow][ycol]     = vl0;
            *(uint4*)&sm.op.Yl[yrow][ycol + 8] = vl1;
        }
        __syncthreads();

        #pragma unroll
        for (int ks = 0; ks < KT; ks += 16) {
            // A fragments (2 M-tiles x hi/lo)
            uint32_t ah[2][4], al[2][4];
            int arow = mpos * 32 + (lane & 15);
            int acol = ks + (lane >> 4) * 8;
            #pragma unroll
            for (int mi = 0; mi < 2; mi++) {
                ldsm_x4(ah[mi], sptr(&sm.op.Wh[arow + mi * 16][acol]));
                ldsm_x4(al[mi], sptr(&sm.op.Wl[arow + mi * 16][acol]));
            }
            int krow  = ks + (lane & 15);
            int bcol0 = npos * 64 + (lane >> 4) * 8;
            #pragma unroll
            for (int nt = 0; nt < 4; nt++) {
                uint32_t bh[4], bl[4];
                ldsm_x4t(bh, sptr(&sm.op.Yh[krow][bcol0 + nt * 16]));
                ldsm_x4t(bl, sptr(&sm.op.Yl[krow][bcol0 + nt * 16]));
                #pragma unroll
                for (int mi = 0; mi < 2; mi++) {
                    #pragma unroll
                    for (int s = 0; s < 2; s++) {
                        float* c = acc[mi][nt * 2 + s];
                        mma16816(c, ah[mi], bh[2 * s], bh[2 * s + 1]);
                        mma16816(c, ah[mi], bl[2 * s], bl[2 * s + 1]);
                        mma16816(c, al[mi], bh[2 * s], bh[2 * s + 1]);
                    }
                }
            }
        }
        __syncthreads();
    }

    // ---- epilogue: GLU via smem exchange ----
    int r0l   = lane >> 2;       // 0..7
    int cpair = (lane & 3) * 2;

    if (mpos >= 2) {             // g-warps: stage sigmoid(g + bg)
        int gbase = (mpos - 2) * 32;
        #pragma unroll
        for (int mi = 0; mi < 2; mi++) {
            #pragma unroll
            for (int rr = 0; rr < 2; rr++) {
                int lr = gbase + mi * 16 + rr * 8 + r0l;
                float bg = bias[Hn + h0 + lr];
                #pragma unroll
                for (int n8 = 0; n8 < 8; n8++) {
                    int col = npos * 64 + n8 * 8 + cpair;
                    float gg0 = acc[mi][n8][rr * 2 + 0] + bg;
                    float gg1 = acc[mi][n8][rr * 2 + 1] + bg;
                    sm.Gs[lr][col]     = 1.0f / (1.0f + expf(-gg0));
                    sm.Gs[lr][col + 1] = 1.0f / (1.0f + expf(-gg1));
                }
            }
        }
    }
    __syncthreads();
    if (mpos < 2) {              // a-warps: a * sigmoid(g), store
        int abase = mpos * 32;
        #pragma unroll
        for (int mi = 0; mi < 2; mi++) {
            #pragma unroll
            for (int rr = 0; rr < 2; rr++) {
                int lr = abase + mi * 16 + rr * 8 + r0l;
                float ba = bias[h0 + lr];
                float* orow = out + (size_t)(b * Hn + h0 + lr) * Ln + c0;
                #pragma unroll
                for (int n8 = 0; n8 < 8; n8++) {
                    int col = npos * 64 + n8 * 8 + cpair;
                    float a0 = acc[mi][n8][rr * 2 + 0] + ba;
                    float a1 = acc[mi][n8][rr * 2 + 1] + ba;
                    float2 o;
                    o.x = a0 * sm.Gs[lr][col];
                    o.y = a1 * sm.Gs[lr][col + 1];
                    *(float2*)&orow[col] = o;
                }
            }
        }
    }
}

// ---------------------------------------------------------------------------
extern "C" void kernel_launch(void* const* d_in, const int* in_sizes, int n_in,
                              void* d_out, int out_size)
{
    const float* u          = (const float*)d_in[0];
    const float* log_dt     = (const float*)d_in[1];
    const float* C_re       = (const float*)d_in[2];
    const float* C_im       = (const float*)d_in[3];
    const float* log_A_real = (const float*)d_in[4];
    const float* A_imag     = (const float*)d_in[5];
    const float* D          = (const float*)d_in[6];
    const float* W          = (const float*)d_in[7];
    const float* bias       = (const float*)d_in[8];
    float* out = (float*)d_out;

    s4d_recurrence<<<(Bn * Hn) / 4, 128>>>(u, log_dt, C_re, C_im,
                                           log_A_real, A_imag, D);

    dim3 grid(Ln / 128, Hn / 64, Bn);   // (32, 8, 8)
    s4d_glu_gemm<<<grid, 256>>>(W, bias, out);
}

// round 13
// speedup vs baseline: 1.0011x; 1.0011x over previous
#include <cuda_runtime.h>
#include <cuda_bf16.h>
#include <math.h>
#include <stdint.h>

#define Bn 8
#define Hn 512
#define Ln 4096
#define NSt 32   // N/2 states

// y = gelu(conv(u,k) + D*u) stored as bf16 hi/lo split (hi + lo ~ fp32-23bit)
__device__ __nv_bfloat16 g_yh[Bn * Hn * Ln];
__device__ __nv_bfloat16 g_yl[Bn * Hn * Ln];

// ---------------------------------------------------------------------------
// Kernel 1: diagonal SSM recurrence + D skip + exact (erf) GELU.
// One warp per (b,h); lane n owns complex state n. Register-array
// recursive-halving reduction (31 shfl per 32 outputs).
// Emits y as bf16 (hi, lo) pair for the tensor-core GEMM.
// ---------------------------------------------------------------------------
__global__ void __launch_bounds__(128)
s4d_recurrence(const float* __restrict__ u,
               const float* __restrict__ log_dt,
               const float* __restrict__ C_re,
               const float* __restrict__ C_im,
               const float* __restrict__ log_A_real,
               const float* __restrict__ A_imag,
               const float* __restrict__ Dv)
{
    int warp = (blockIdx.x * blockDim.x + threadIdx.x) >> 5;
    int lane = threadIdx.x & 31;
    if (warp >= Bn * Hn) return;
    int b = warp / Hn;
    int h = warp % Hn;

    float dt  = expf(log_dt[h]);
    float Are = -expf(log_A_real[h * NSt + lane]);
    float Aim = A_imag[h * NSt + lane];
    float dAr = Are * dt, dAi = Aim * dt;
    float er  = expf(dAr);
    float sv, cv;
    sincosf(dAi, &sv, &cv);
    float wr = er * cv, wi = er * sv;          // w = exp(dt*A)
    float cr = C_re[h * NSt + lane];
    float ci = C_im[h * NSt + lane];
    // Ck = 2*C*(w-1)/A
    float m1r = wr - 1.0f;
    float nr  = cr * m1r - ci * wi;
    float ni  = cr * wi  + ci * m1r;
    float inv = 2.0f / (Are * Are + Aim * Aim);
    float Ckr = (nr * Are + ni * Aim) * inv;
    float Cki = (ni * Are - nr * Aim) * inv;

    float Dh = Dv[h];
    const float*   up  = u    + (size_t)(b * Hn + h) * Ln;
    __nv_bfloat16* yph = g_yh + (size_t)(b * Hn + h) * Ln;
    __nv_bfloat16* ypl = g_yl + (size_t)(b * Hn + h) * Ln;

    float sr = 0.0f, si = 0.0f;
    for (int l0 = 0; l0 < Ln; l0 += 32) {
        float uv = up[l0 + lane];
        float p[32];
        #pragma unroll
        for (int j = 0; j < 32; ++j) {
            float uj  = __shfl_sync(0xffffffffu, uv, j);
            float t   = fmaf(wr, sr, uj);
            float nsi = fmaf(wr, si, wi * sr);
            sr = fmaf(-wi, si, t);
            si = nsi;
            p[j] = fmaf(Ckr, sr, -(Cki * si));
        }
        #pragma unroll
        for (int mask = 16; mask >= 1; mask >>= 1) {
            bool hi = (lane & mask) != 0;
            #pragma unroll
            for (int j = 0; j < 32; ++j) {
                if (j >= mask) continue;
                float mine = hi ? p[j] : p[j + mask];
                float keep = hi ? p[j + mask] : p[j];
                p[j] = keep + __shfl_xor_sync(0xffffffffu, mine, mask);
            }
        }
        float yraw = fmaf(Dh, uv, p[0]);
        float yg   = yraw * normcdff(yraw);     // exact GELU
        __nv_bfloat16 hh = __float2bfloat16(yg);
        __nv_bfloat16 ll = __float2bfloat16(yg - __bfloat162float(hh));
        yph[l0 + lane] = hh;
        ypl[l0 + lane] = ll;
    }
}

// ---------------------------------------------------------------------------
// Kernel 2: tensor-core GEMM (2H x H) @ (H x L) + bias + GLU.
// bf16 split-precision: acc = Whi@Yhi + Whi@Ylo + Wlo@Yhi (fp32 accum).
// CTA tile: 64 h-rows (both a and g halves => 128 W rows) x 128 l-cols, KT=32.
// 8 warps: mpos = wid&3 (a0,a1,g0,g1 row quads of 32), npos = wid>>2.
// Epilogue: g-warps stage sigmoid(g+bg) in smem; a-warps multiply + store.
// ---------------------------------------------------------------------------
#define KT 32

struct SmemOps {
    __nv_bfloat16 Wh[128][40];   // [row][k], pad -> 80B stride (conflict-free)
    __nv_bfloat16 Wl[128][40];
    __nv_bfloat16 Yh[KT][136];   // [k][col], pad -> 272B stride
    __nv_bfloat16 Yl[KT][136];
};
union SmemGemm {
    SmemOps op;
    float   Gs[64][132];         // sigmoid(g) staging for GLU epilogue
};

__device__ __forceinline__ uint32_t sptr(const void* p) {
    return (uint32_t)__cvta_generic_to_shared(p);
}
__device__ __forceinline__ void ldsm_x4(uint32_t* r, uint32_t addr) {
    asm volatile("ldmatrix.sync.aligned.m8n8.x4.shared.b16 {%0,%1,%2,%3}, [%4];"
                 : "=r"(r[0]), "=r"(r[1]), "=r"(r[2]), "=r"(r[3]) : "r"(addr));
}
__device__ __forceinline__ void ldsm_x4t(uint32_t* r, uint32_t addr) {
    asm volatile("ldmatrix.sync.aligned.m8n8.x4.trans.shared.b16 {%0,%1,%2,%3}, [%4];"
                 : "=r"(r[0]), "=r"(r[1]), "=r"(r[2]), "=r"(r[3]) : "r"(addr));
}
__device__ __forceinline__ void mma16816(float* c, const uint32_t* a,
                                         uint32_t b0, uint32_t b1) {
    asm volatile(
        "mma.sync.aligned.m16n8k16.row.col.f32.bf16.bf16.f32 "
        "{%0,%1,%2,%3}, {%4,%5,%6,%7}, {%8,%9}, {%0,%1,%2,%3};"
        : "+f"(c[0]), "+f"(c[1]), "+f"(c[2]), "+f"(c[3])
        : "r"(a[0]), "r"(a[1]), "r"(a[2]), "r"(a[3]), "r"(b0), "r"(b1));
}

__global__ void __launch_bounds__(256, 2)
s4d_glu_gemm(const float* __restrict__ Wm,
             const float* __restrict__ bias,
             float* __restrict__ out)
{
    __shared__ SmemGemm sm;

    int b   = blockIdx.z;
    int h0  = blockIdx.y * 64;
    int c0  = blockIdx.x * 128;
    int tid = threadIdx.x;
    int wid = tid >> 5, lane = tid & 31;
    int mpos = wid & 3;          // 0,1 -> a rows; 2,3 -> g rows
    int npos = wid >> 2;         // 0,1 -> col halves of 64

    float acc[2][8][4];          // [mi (16-row tile)][n8 tile][frag]
    #pragma unroll
    for (int i = 0; i < 2; i++)
        #pragma unroll
        for (int j = 0; j < 8; j++)
            #pragma unroll
            for (int v = 0; v < 4; v++) acc[i][j][v] = 0.0f;

    // load mappings
    int wrow = tid >> 1;                 // 0..127 (W tile row)
    int wcol = (tid & 1) * 16;           // k offset within KT
    int grow = (wrow < 64) ? (h0 + wrow) : (Hn + h0 + wrow - 64);
    const float* wsrc = Wm + (size_t)grow * Hn;

    int yrow = tid >> 3;                 // 0..31
    int ycol = (tid & 7) * 16;           // 0..112

    const __nv_bfloat16* ysh = g_yh + (size_t)b * Hn * Ln;
    const __nv_bfloat16* ysl = g_yl + (size_t)b * Hn * Ln;

    for (int kt = 0; kt < Hn; kt += KT) {
        // --- stage W (fp32 -> bf16 hi/lo) ---
        #pragma unroll
        for (int j = 0; j < 4; j++) {
            float4 v = *(const float4*)&wsrc[kt + wcol + 4 * j];
            __nv_bfloat162 h0p = __floats2bfloat162_rn(v.x, v.y);
            __nv_bfloat162 h1p = __floats2bfloat162_rn(v.z, v.w);
            float lx = v.x - __bfloat162float(h0p.x);
            float ly = v.y - __bfloat162float(h0p.y);
            float lz = v.z - __bfloat162float(h1p.x);
            float lw = v.w - __bfloat162float(h1p.y);
            __nv_bfloat162 l0p = __floats2bfloat162_rn(lx, ly);
            __nv_bfloat162 l1p = __floats2bfloat162_rn(lz, lw);
            *(__nv_bfloat162*)&sm.op.Wh[wrow][wcol + 4 * j]     = h0p;
            *(__nv_bfloat162*)&sm.op.Wh[wrow][wcol + 4 * j + 2] = h1p;
            *(__nv_bfloat162*)&sm.op.Wl[wrow][wcol + 4 * j]     = l0p;
            *(__nv_bfloat162*)&sm.op.Wl[wrow][wcol + 4 * j + 2] = l1p;
        }
        // --- stage Y (already bf16 hi/lo) ---
        {
            size_t gy = (size_t)(kt + yrow) * Ln + c0 + ycol;
            uint4 vh0 = *(const uint4*)&ysh[gy];
            uint4 vh1 = *(const uint4*)&ysh[gy + 8];
            uint4 vl0 = *(const uint4*)&ysl[gy];
            uint4 vl1 = *(const uint4*)&ysl[gy + 8];
            *(uint4*)&sm.op.Yh[yrow][ycol]     = vh0;
            *(uint4*)&sm.op.Yh[yrow][ycol + 8] = vh1;
            *(uint4*)&sm.op.Yl[yrow][ycol]     = vl0;
            *(uint4*)&sm.op.Yl[yrow][ycol + 8] = vl1;
        }
        __syncthreads();

        #pragma unroll
        for (int ks = 0; ks < KT; ks += 16) {
            // A fragments (2 M-tiles x hi/lo)
            uint32_t ah[2][4], al[2][4];
            int arow = mpos * 32 + (lane & 15);
            int acol = ks + (lane >> 4) * 8;
            #pragma unroll
            for (int mi = 0; mi < 2; mi++) {
                ldsm_x4(ah[mi], sptr(&sm.op.Wh[arow + mi * 16][acol]));
                ldsm_x4(al[mi], sptr(&sm.op.Wl[arow + mi * 16][acol]));
            }
            int krow  = ks + (lane & 15);
            int bcol0 = npos * 64 + (lane >> 4) * 8;
            #pragma unroll
            for (int nt = 0; nt < 4; nt++) {
                uint32_t bh[4], bl[4];
                ldsm_x4t(bh, sptr(&sm.op.Yh[krow][bcol0 + nt * 16]));
                ldsm_x4t(bl, sptr(&sm.op.Yl[krow][bcol0 + nt * 16]));
                #pragma unroll
                for (int mi = 0; mi < 2; mi++) {
                    #pragma unroll
                    for (int s = 0; s < 2; s++) {
                        float* c = acc[mi][nt * 2 + s];
                        mma16816(c, ah[mi], bh[2 * s], bh[2 * s + 1]);
                        mma16816(c, ah[mi], bl[2 * s], bl[2 * s + 1]);
                        mma16816(c, al[mi], bh[2 * s], bh[2 * s + 1]);
                    }
                }
            }
        }
        __syncthreads();
    }

    // ---- epilogue: GLU via smem exchange ----
    int r0l   = lane >> 2;       // 0..7
    int cpair = (lane & 3) * 2;

    if (mpos >= 2) {             // g-warps: stage sigmoid(g + bg)
        int gbase = (mpos - 2) * 32;
        #pragma unroll
        for (int mi = 0; mi < 2; mi++) {
            #pragma unroll
            for (int rr = 0; rr < 2; rr++) {
                int lr = gbase + mi * 16 + rr * 8 + r0l;
                float bg = bias[Hn + h0 + lr];
                #pragma unroll
                for (int n8 = 0; n8 < 8; n8++) {
                    int col = npos * 64 + n8 * 8 + cpair;
                    float gg0 = acc[mi][n8][rr * 2 + 0] + bg;
                    float gg1 = acc[mi][n8][rr * 2 + 1] + bg;
                    sm.Gs[lr][col]     = 1.0f / (1.0f + expf(-gg0));
                    sm.Gs[lr][col + 1] = 1.0f / (1.0f + expf(-gg1));
                }
            }
        }
    }
    __syncthreads();
    if (mpos < 2) {              // a-warps: a * sigmoid(g), store
        int abase = mpos * 32;
        #pragma unroll
        for (int mi = 0; mi < 2; mi++) {
            #pragma unroll
            for (int rr = 0; rr < 2; rr++) {
                int lr = abase + mi * 16 + rr * 8 + r0l;
                float ba = bias[h0 + lr];
                float* orow = out + (size_t)(b * Hn + h0 + lr) * Ln + c0;
                #pragma unroll
                for (int n8 = 0; n8 < 8; n8++) {
                    int col = npos * 64 + n8 * 8 + cpair;
                    float a0 = acc[mi][n8][rr * 2 + 0] + ba;
                    float a1 = acc[mi][n8][rr * 2 + 1] + ba;
                    float2 o;
                    o.x = a0 * sm.Gs[lr][col];
                    o.y = a1 * sm.Gs[lr][col + 1];
                    *(float2*)&orow[col] = o;
                }
            }
        }
    }
}

// ---------------------------------------------------------------------------
extern "C" void kernel_launch(void* const* d_in, const int* in_sizes, int n_in,
                              void* d_out, int out_size)
{
    const float* u          = (const float*)d_in[0];
    const float* log_dt     = (const float*)d_in[1];
    const float* C_re       = (const float*)d_in[2];
    const float* C_im       = (const float*)d_in[3];
    const float* log_A_real = (const float*)d_in[4];
    const float* A_imag     = (const float*)d_in[5];
    const float* D          = (const float*)d_in[6];
    const float* W          = (const float*)d_in[7];
    const float* bias       = (const float*)d_in[8];
    float* out = (float*)d_out;

    s4d_recurrence<<<(Bn * Hn) / 4, 128>>>(u, log_dt, C_re, C_im,
                                           log_A_real, A_imag, D);

    dim3 grid(Ln / 128, Hn / 64, Bn);   // (32, 8, 8)
    s4d_glu_gemm<<<grid, 256>>>(W, bias, out);
}